// round 1
// baseline (speedup 1.0000x reference)
#include <cuda_runtime.h>

typedef unsigned long long ull;

#define HIDDEN 2048
#define HEADS 16
#define HD 128
#define NB 2
#define SEQ 2048
#define MTOT (NB*SEQ)   // 4096

// ---------------- scratch (static device allocations; no cudaMalloc) -------
__device__ float g_q[(size_t)NB*HEADS*SEQ*HD];     // [B,H,S,Hd]
__device__ float g_k[(size_t)NB*HEADS*SEQ*HD];
__device__ float g_v[(size_t)NB*HEADS*SEQ*HD];
__device__ float g_ctx[(size_t)MTOT*HIDDEN];       // attention output, [B*S, D]
__device__ float g_cos[SEQ*64];
__device__ float g_sin[SEQ*64];

// ---------------- f32x2 packed helpers (Blackwell FFMA2 path) --------------
__device__ __forceinline__ ull pack2(float lo, float hi) {
    ull d;
    asm("mov.b64 %0, {%1, %2};" : "=l"(d)
        : "r"(__float_as_uint(lo)), "r"(__float_as_uint(hi)));
    return d;
}
__device__ __forceinline__ void unpack2(ull d, float& lo, float& hi) {
    unsigned a, b;
    asm("mov.b64 {%0, %1}, %2;" : "=r"(a), "=r"(b) : "l"(d));
    lo = __uint_as_float(a); hi = __uint_as_float(b);
}
__device__ __forceinline__ void fma2(ull& c, ull a, ull b) {
    asm("fma.rn.f32x2 %0, %1, %2, %3;" : "=l"(c) : "l"(a), "l"(b), "l"(c));
}
__device__ __forceinline__ void mul2(ull& c, ull a, ull b) {
    asm("mul.rn.f32x2 %0, %1, %2;" : "=l"(c) : "l"(a), "l"(b));
}

// ---------------- RoPE cos/sin table (fp64 math -> fp32 table) -------------
__global__ void rope_table_kernel() {
    int idx = blockIdx.x * blockDim.x + threadIdx.x;
    if (idx >= SEQ * 64) return;
    int s = idx >> 6, i = idx & 63;
    double invf = pow(10000.0, -(double)i / 64.0);
    double ang = (double)s * invf;
    g_cos[idx] = (float)cos(ang);
    g_sin[idx] = (float)sin(ang);
}

// ---------------- RoPE apply (in place on g_q, g_k) ------------------------
__global__ void rope_apply_kernel() {
    long idx = (long)blockIdx.x * blockDim.x + threadIdx.x;  // B*H*S*64 threads
    if (idx >= (long)NB * HEADS * SEQ * 64) return;
    int i = (int)(idx & 63);
    long t = idx >> 6;
    int s = (int)(t & (SEQ - 1));
    long bh = t >> 11;                       // t / SEQ
    long base = (bh * SEQ + s) * HD;
    float c = g_cos[s * 64 + i], sn = g_sin[s * 64 + i];
    float q1 = g_q[base + i], q2 = g_q[base + i + 64];
    g_q[base + i]      = q1 * c - q2 * sn;
    g_q[base + i + 64] = q2 * c + q1 * sn;
    float k1 = g_k[base + i], k2 = g_k[base + i + 64];
    g_k[base + i]      = k1 * c - k2 * sn;
    g_k[base + i + 64] = k2 * c + k1 * sn;
}

// ---------------- GEMM: C[M,N] = A[M,K] * W[N,K]^T (nn.Linear) -------------
// 128x128 tile, BK=16, 256 threads, f32x2 packed accumulation.
// head_mode=1: write to [B,H,S,Hd] layout; head_mode=0: plain row-major.
__global__ __launch_bounds__(256)
void gemm_abt(const float* __restrict__ A, const float* __restrict__ W,
              float* __restrict__ out, int head_mode)
{
    __shared__ float As[16][128];   // k-major
    __shared__ float Bs[16][128];
    int tid = threadIdx.x;
    int tx = tid & 15, ty = tid >> 4;
    int n0 = blockIdx.x * 128;
    int m0 = blockIdx.y * 128;
    const float* Arow = A + (long)m0 * HIDDEN;
    const float* Wrow = W + (long)n0 * HIDDEN;

    ull acc[8][4];
    #pragma unroll
    for (int i = 0; i < 8; i++)
        #pragma unroll
        for (int j = 0; j < 4; j++) acc[i][j] = 0ULL;   // (0.f, 0.f)

    for (int k0 = 0; k0 < HIDDEN; k0 += 16) {
        #pragma unroll
        for (int it = 0; it < 2; it++) {
            int f = it * 256 + tid;
            int r = f >> 2, kc = (f & 3) << 2;
            float4 va = *(const float4*)(Arow + (long)r * HIDDEN + k0 + kc);
            As[kc + 0][r] = va.x; As[kc + 1][r] = va.y;
            As[kc + 2][r] = va.z; As[kc + 3][r] = va.w;
            float4 vb = *(const float4*)(Wrow + (long)r * HIDDEN + k0 + kc);
            Bs[kc + 0][r] = vb.x; Bs[kc + 1][r] = vb.y;
            Bs[kc + 2][r] = vb.z; Bs[kc + 3][r] = vb.w;
        }
        __syncthreads();
        #pragma unroll
        for (int kk = 0; kk < 16; kk++) {
            // a: 8 row values (broadcast within warp), duplicated into pairs
            ull adup[8];
            #pragma unroll
            for (int ip = 0; ip < 4; ip++) {
                ull av = *(const ull*)&As[kk][ty * 8 + ip * 2];
                float lo, hi; unpack2(av, lo, hi);
                adup[2 * ip]     = pack2(lo, lo);
                adup[2 * ip + 1] = pack2(hi, hi);
            }
            // b: 4 natural column pairs (cols 2*tx+32*jj, +1)
            ull b2[4];
            #pragma unroll
            for (int jj = 0; jj < 4; jj++)
                b2[jj] = *(const ull*)&Bs[kk][2 * tx + 32 * jj];
            #pragma unroll
            for (int i = 0; i < 8; i++)
                #pragma unroll
                for (int jj = 0; jj < 4; jj++)
                    fma2(acc[i][jj], adup[i], b2[jj]);
        }
        __syncthreads();
    }

    #pragma unroll
    for (int i = 0; i < 8; i++) {
        int m = m0 + ty * 8 + i;
        int bb = m >> 11, s = m & (SEQ - 1);
        #pragma unroll
        for (int jj = 0; jj < 4; jj++) {
            float lo, hi; unpack2(acc[i][jj], lo, hi);
            int n = n0 + 2 * tx + 32 * jj;
            if (head_mode) {
                int h = n >> 7, d = n & 127;     // d even, d+1 same head
                long o = (((long)(bb * HEADS + h)) * SEQ + s) * HD + d;
                out[o] = lo; out[o + 1] = hi;
            } else {
                *(float2*)&out[(long)m * HIDDEN + n] = make_float2(lo, hi);
            }
        }
    }
}

// ---------------- Flash-style causal attention ------------------------------
// Block = (q-tile of 64 rows) x (one bh). 256 threads. BKV=64.
#define QPAD 132
#define SPAD 68
#define ATTN_SMEM_FLOATS (64*QPAD + 64*QPAD + 64*HD + 64*SPAD + 3*64)
#define ATTN_SMEM_BYTES  (ATTN_SMEM_FLOATS * 4)

__global__ __launch_bounds__(256)
void attn_kernel()
{
    extern __shared__ float sm[];
    float* Qs   = sm;                    // [64][132], pre-scaled
    float* Ks   = Qs + 64 * QPAD;        // [64][132]
    float* Vs   = Ks + 64 * QPAD;        // [64][128]
    float* Ss   = Vs + 64 * HD;          // [64][68]
    float* mrow = Ss + 64 * SPAD;
    float* lrow = mrow + 64;
    float* crow = lrow + 64;

    int tid = threadIdx.x;
    int tc = tid & 15, tr = tid >> 4;
    int qt = gridDim.x - 1 - blockIdx.x; // heavy tiles first
    int bh = blockIdx.y;
    const float scale = 0.08838834764831845f; // 1/sqrt(128)
    long qbase = ((long)bh * SEQ + (long)qt * 64) * HD;

    // load + scale Q tile
    #pragma unroll
    for (int it = 0; it < 8; it++) {
        int f = it * 256 + tid;
        int r = f >> 5, c4 = (f & 31) << 2;
        float4 v = *(const float4*)&g_q[qbase + (long)r * HD + c4];
        v.x *= scale; v.y *= scale; v.z *= scale; v.w *= scale;
        *(float4*)&Qs[r * QPAD + c4] = v;
    }
    if (tid < 64) { mrow[tid] = -__int_as_float(0x7f800000); lrow[tid] = 0.f; }

    ull accO[4][8];
    #pragma unroll
    for (int i = 0; i < 4; i++)
        #pragma unroll
        for (int u = 0; u < 8; u++) accO[i][u] = 0ULL;

    __syncthreads();

    for (int kt = 0; kt <= qt; kt++) {
        long kvbase = ((long)bh * SEQ + (long)kt * 64) * HD;
        #pragma unroll
        for (int it = 0; it < 8; it++) {
            int f = it * 256 + tid;
            int r = f >> 5, c4 = (f & 31) << 2;
            *(float4*)&Ks[r * QPAD + c4] = *(const float4*)&g_k[kvbase + (long)r * HD + c4];
            *(float4*)&Vs[r * HD  + c4] = *(const float4*)&g_v[kvbase + (long)r * HD + c4];
        }
        __syncthreads();

        // scores: rows tr*4+i, cols tc+16*j ; packed over k pairs
        ull sacc[4][4];
        #pragma unroll
        for (int i = 0; i < 4; i++)
            #pragma unroll
            for (int j = 0; j < 4; j++) sacc[i][j] = 0ULL;

        #pragma unroll 8
        for (int k = 0; k < HD; k += 2) {
            ull q2[4], k2[4];
            #pragma unroll
            for (int i = 0; i < 4; i++)
                q2[i] = *(const ull*)&Qs[(tr * 4 + i) * QPAD + k];
            #pragma unroll
            for (int j = 0; j < 4; j++)
                k2[j] = *(const ull*)&Ks[(tc + 16 * j) * QPAD + k];
            #pragma unroll
            for (int i = 0; i < 4; i++)
                #pragma unroll
                for (int j = 0; j < 4; j++)
                    fma2(sacc[i][j], q2[i], k2[j]);
        }

        bool diag = (kt == qt);
        #pragma unroll
        for (int i = 0; i < 4; i++) {
            int r = tr * 4 + i;
            #pragma unroll
            for (int j = 0; j < 4; j++) {
                int c = tc + 16 * j;
                float lo, hi; unpack2(sacc[i][j], lo, hi);
                float v = lo + hi;
                if (diag && c > r) v = -__int_as_float(0x7f800000); // -inf
                Ss[r * SPAD + c] = v;
            }
        }
        __syncthreads();

        // online softmax, one thread per row
        if (tid < 64) {
            int r = tid;
            float mo = mrow[r];
            float mx = mo;
            #pragma unroll 8
            for (int c = 0; c < 64; c++) mx = fmaxf(mx, Ss[r * SPAD + c]);
            float co = __expf(mo - mx);
            float sum = 0.f;
            #pragma unroll 8
            for (int c = 0; c < 64; c++) {
                float p = __expf(Ss[r * SPAD + c] - mx);
                Ss[r * SPAD + c] = p;
                sum += p;
            }
            crow[r] = co;
            lrow[r] = lrow[r] * co + sum;
            mrow[r] = mx;
        }
        __syncthreads();

        // rescale accumulators + P@V (packed over kk pairs)
        #pragma unroll
        for (int i = 0; i < 4; i++) {
            float cf = crow[tr * 4 + i];
            ull cf2 = pack2(cf, cf);
            #pragma unroll
            for (int u = 0; u < 8; u++) mul2(accO[i][u], accO[i][u], cf2);
        }
        #pragma unroll 4
        for (int kk = 0; kk < 64; kk += 2) {
            ull p2[4];
            #pragma unroll
            for (int i = 0; i < 4; i++)
                p2[i] = *(const ull*)&Ss[(tr * 4 + i) * SPAD + kk];
            #pragma unroll
            for (int u = 0; u < 8; u++) {
                int c = tc + 16 * u;
                ull v2 = pack2(Vs[kk * HD + c], Vs[(kk + 1) * HD + c]);
                #pragma unroll
                for (int i = 0; i < 4; i++)
                    fma2(accO[i][u], p2[i], v2);
            }
        }
        __syncthreads();
    }

    // epilogue -> g_ctx[B*S, D] with col = h*128 + d
    int bb = bh >> 4, h = bh & 15;
    #pragma unroll
    for (int i = 0; i < 4; i++) {
        int r = tr * 4 + i;
        float invl = 1.0f / lrow[r];
        long rowbase = ((long)(bb * SEQ + qt * 64 + r)) * HIDDEN + h * HD;
        #pragma unroll
        for (int u = 0; u < 8; u++) {
            float lo, hi; unpack2(accO[i][u], lo, hi);
            g_ctx[rowbase + tc + 16 * u] = (lo + hi) * invl;
        }
    }
}

// ---------------- launcher --------------------------------------------------
extern "C" void kernel_launch(void* const* d_in, const int* in_sizes, int n_in,
                              void* d_out, int out_size)
{
    (void)in_sizes; (void)n_in; (void)out_size;
    const float* X  = (const float*)d_in[0];
    const float* wq = (const float*)d_in[1];
    const float* wk = (const float*)d_in[2];
    const float* wv = (const float*)d_in[3];
    const float* wo = (const float*)d_in[4];
    float* out = (float*)d_out;

    float *qp, *kp, *vp, *ctxp;
    cudaGetSymbolAddress((void**)&qp,  g_q);
    cudaGetSymbolAddress((void**)&kp,  g_k);
    cudaGetSymbolAddress((void**)&vp,  g_v);
    cudaGetSymbolAddress((void**)&ctxp, g_ctx);

    cudaFuncSetAttribute(attn_kernel,
                         cudaFuncAttributeMaxDynamicSharedMemorySize,
                         ATTN_SMEM_BYTES);

    rope_table_kernel<<<(SEQ * 64 + 255) / 256, 256>>>();

    dim3 gg(HIDDEN / 128, MTOT / 128);       // (16, 32)
    gemm_abt<<<gg, 256>>>(X, wq, qp, 1);
    gemm_abt<<<gg, 256>>>(X, wk, kp, 1);
    gemm_abt<<<gg, 256>>>(X, wv, vp, 1);

    long rope_threads = (long)NB * HEADS * SEQ * 64;
    rope_apply_kernel<<<(unsigned)((rope_threads + 255) / 256), 256>>>();

    attn_kernel<<<dim3(SEQ / 64, NB * HEADS), 256, ATTN_SMEM_BYTES>>>();

    gemm_abt<<<gg, 256>>>(ctxp, wo, out, 0);
}

// round 3
// speedup vs baseline: 1.5945x; 1.5945x over previous
#include <cuda_runtime.h>
#include <cuda_bf16.h>
#include <cstdint>

typedef unsigned long long ull;

#define HIDDEN 2048
#define K3     6144          // 3 * HIDDEN (bf16x3 split along K)
#define HEADS  16
#define HD     128
#define NB     2
#define SEQ    2048
#define MTOT   4096
#define BK     32
#define NSTAGE (K3/BK)       // 192

// ---------------- scratch (static device allocations) ----------------------
__device__ __align__(128) __nv_bfloat16 g_Xp[(size_t)MTOT*K3];
__device__ __align__(128) __nv_bfloat16 g_Wp[4][(size_t)HIDDEN*K3];
__device__ __align__(128) __nv_bfloat16 g_Cp[(size_t)MTOT*K3];
__device__ float g_q[(size_t)NB*HEADS*SEQ*HD];     // [B,H,S,Hd] rope+scale applied
__device__ float g_k[(size_t)NB*HEADS*SEQ*HD];
__device__ float g_v[(size_t)NB*HEADS*SEQ*HD];
__device__ float g_ctx[(size_t)MTOT*HIDDEN];
__device__ float g_cos[SEQ*64];
__device__ float g_sin[SEQ*64];

// ---------------- f32x2 packed helpers --------------------------------------
__device__ __forceinline__ ull pack2(float lo, float hi) {
    ull d;
    asm("mov.b64 %0, {%1, %2};" : "=l"(d)
        : "r"(__float_as_uint(lo)), "r"(__float_as_uint(hi)));
    return d;
}
__device__ __forceinline__ void unpack2(ull d, float& lo, float& hi) {
    unsigned a, b;
    asm("mov.b64 {%0, %1}, %2;" : "=r"(a), "=r"(b) : "l"(d));
    lo = __uint_as_float(a); hi = __uint_as_float(b);
}
__device__ __forceinline__ void fma2(ull& c, ull a, ull b) {
    asm("fma.rn.f32x2 %0, %1, %2, %3;" : "=l"(c) : "l"(a), "l"(b), "l"(c));
}
__device__ __forceinline__ void mul2(ull& c, ull a, ull b) {
    asm("mul.rn.f32x2 %0, %1, %2;" : "=l"(c) : "l"(a), "l"(b));
}

// ---------------- mma.sync bf16 (non-'a' PTX, runs on tensor pipe) ----------
__device__ __forceinline__ void mma16816(float* c, const uint32_t* a, const uint32_t* b) {
    asm volatile(
        "mma.sync.aligned.m16n8k16.row.col.f32.bf16.bf16.f32 "
        "{%0,%1,%2,%3}, {%4,%5,%6,%7}, {%8,%9}, {%0,%1,%2,%3};"
        : "+f"(c[0]), "+f"(c[1]), "+f"(c[2]), "+f"(c[3])
        : "r"(a[0]), "r"(a[1]), "r"(a[2]), "r"(a[3]), "r"(b[0]), "r"(b[1]));
}
__device__ __forceinline__ void cp_async16(uint32_t saddr, const void* gaddr) {
    asm volatile("cp.async.ca.shared.global [%0], [%1], 16;"
                 :: "r"(saddr), "l"(gaddr));
}
__device__ __forceinline__ uint32_t smem_u32(const void* p) {
    uint32_t a;
    asm("{ .reg .u64 t; cvta.to.shared.u64 t, %1; cvt.u32.u64 %0, t; }" : "=r"(a) : "l"(p));
    return a;
}

// ---------------- RoPE cos/sin table ----------------------------------------
__global__ void rope_table_kernel() {
    int idx = blockIdx.x * blockDim.x + threadIdx.x;
    if (idx >= SEQ * 64) return;
    int s = idx >> 6, i = idx & 63;
    double invf = pow(10000.0, -(double)i / 64.0);
    double ang = (double)s * invf;
    g_cos[idx] = (float)cos(ang);
    g_sin[idx] = (float)sin(ang);
}

// ---------------- bf16x3 split conversion -----------------------------------
// wmode=0 (A): [k]=hi, [2048+k]=hi, [4096+k]=lo
// wmode=1 (W): [k]=hi, [2048+k]=lo, [4096+k]=hi
__global__ void convert_split(const float* __restrict__ src,
                              __nv_bfloat16* __restrict__ dst,
                              int rows, int wmode) {
    long idx = (long)blockIdx.x * blockDim.x + threadIdx.x;
    if (idx >= (long)rows * HIDDEN) return;
    long r = idx >> 11; int k = (int)(idx & 2047);
    float x = src[idx];
    __nv_bfloat16 h = __float2bfloat16(x);
    __nv_bfloat16 l = __float2bfloat16(x - __bfloat162float(h));
    __nv_bfloat16* d = dst + r * K3;
    d[k] = h;
    d[HIDDEN + k]     = wmode ? l : h;
    d[2 * HIDDEN + k] = wmode ? h : l;
}

// ---------------- mma.sync GEMM: D[M,N] = A'[M,K3] * W'[N,K3]^T --------------
// 128x128 tile, 256 threads (8 warps, 2x4), BK=32, cp.async double buffer.
// SMEM tile rows padded to 80B -> conflict-free fragment LDS.
// fused=1: blockIdx.x in [0,48): which=x>>4 selects Q/K/V (mode 0/1/2)
// fused=0: plain row-major output (mode 3)
#define TILE_STRIDE 80                    // bytes per 32-bf16 row (64B + 16B pad)
#define A_ST_SZ     (128*TILE_STRIDE)     // 10240
#define G_SMEM_BYTES (128*132*4)          // 67584 (epilogue Osm; tiles alias low 40KB)

__global__ __launch_bounds__(256)
void gemm_mma(const __nv_bfloat16* __restrict__ A,
              const __nv_bfloat16* __restrict__ Wq,
              const __nv_bfloat16* __restrict__ Wk,
              const __nv_bfloat16* __restrict__ Wv,
              float* __restrict__ Dq, float* __restrict__ Dk, float* __restrict__ Dv,
              int fused)
{
    extern __shared__ char smem[];
    uint32_t sb = smem_u32(smem);
    int tid = threadIdx.x;
    int wid = tid >> 5, lane = tid & 31;
    int warpm = wid >> 2, warpn = wid & 3;     // 2 x 4 warp grid
    int lrow = lane >> 2, lk = lane & 3;

    const __nv_bfloat16* W; float* D; int n0, mode;
    if (fused) {
        int which = blockIdx.x >> 4;
        n0 = (blockIdx.x & 15) * 128;
        W = (which == 0) ? Wq : (which == 1) ? Wk : Wv;
        D = (which == 0) ? Dq : (which == 1) ? Dk : Dv;
        mode = which;
    } else {
        n0 = blockIdx.x * 128; W = Wq; D = Dq; mode = 3;
    }
    int m0 = blockIdx.y * 128;

    const char* Ab = (const char*)(A + (size_t)m0 * K3);
    const char* Bb = (const char*)(W + (size_t)n0 * K3);

    float acc[4][4][4];
    #pragma unroll
    for (int i = 0; i < 4; i++)
        #pragma unroll
        for (int j = 0; j < 4; j++)
            #pragma unroll
            for (int r = 0; r < 4; r++) acc[i][j][r] = 0.f;

    // stage issue: A tile 128x32bf16 (64B/row) + B tile, each 512 16B-chunks
    int ld_r = tid >> 2, ld_c = (tid & 3) * 16;       // chunk 0 of this thread
    auto issue_stage = [&](int kelem, int buf) {
        uint32_t sA = sb + buf * A_ST_SZ;
        uint32_t sB = sb + 2 * A_ST_SZ + buf * A_ST_SZ;
        const char* gA = Ab + (size_t)kelem * 2;
        const char* gB = Bb + (size_t)kelem * 2;
        #pragma unroll
        for (int it = 0; it < 2; it++) {
            int r = ld_r + it * 64;
            cp_async16(sA + r * TILE_STRIDE + ld_c, gA + (size_t)r * (K3 * 2) + ld_c);
            cp_async16(sB + r * TILE_STRIDE + ld_c, gB + (size_t)r * (K3 * 2) + ld_c);
        }
        asm volatile("cp.async.commit_group;" ::: "memory");
    };

    issue_stage(0, 0);

    for (int st = 0; st < NSTAGE; st++) {
        if (st + 1 < NSTAGE) {
            issue_stage((st + 1) * BK, (st + 1) & 1);
            asm volatile("cp.async.wait_group 1;" ::: "memory");
        } else {
            asm volatile("cp.async.wait_group 0;" ::: "memory");
        }
        __syncthreads();

        int buf = st & 1;
        const char* aB = smem + buf * A_ST_SZ;
        const char* bB = smem + 2 * A_ST_SZ + buf * A_ST_SZ;

        #pragma unroll
        for (int s = 0; s < 2; s++) {            // two k16 steps in BK=32
            uint32_t afr[4][4], bfr[4][2];
            #pragma unroll
            for (int i = 0; i < 4; i++) {
                const char* p = aB + (warpm * 64 + i * 16 + lrow) * TILE_STRIDE
                                   + (s * 8 + lk) * 4;
                afr[i][0] = *(const uint32_t*)p;
                afr[i][1] = *(const uint32_t*)(p + 8 * TILE_STRIDE);
                afr[i][2] = *(const uint32_t*)(p + 16);
                afr[i][3] = *(const uint32_t*)(p + 8 * TILE_STRIDE + 16);
            }
            #pragma unroll
            for (int j = 0; j < 4; j++) {
                const char* p = bB + (warpn * 32 + j * 8 + lrow) * TILE_STRIDE
                                   + (s * 8 + lk) * 4;
                bfr[j][0] = *(const uint32_t*)p;
                bfr[j][1] = *(const uint32_t*)(p + 16);
            }
            #pragma unroll
            for (int i = 0; i < 4; i++)
                #pragma unroll
                for (int j = 0; j < 4; j++)
                    mma16816(acc[i][j], afr[i], bfr[j]);
        }
        __syncthreads();
    }

    // ---- epilogue: regs -> SMEM (Osm 128x132), then fused RoPE writes ----
    float* Osm = (float*)smem;
    #pragma unroll
    for (int i = 0; i < 4; i++) {
        int r0 = warpm * 64 + i * 16 + lrow;
        #pragma unroll
        for (int j = 0; j < 4; j++) {
            int c0 = warpn * 32 + j * 8 + lk * 2;
            Osm[r0 * 132 + c0]           = acc[i][j][0];
            Osm[r0 * 132 + c0 + 1]       = acc[i][j][1];
            Osm[(r0 + 8) * 132 + c0]     = acc[i][j][2];
            Osm[(r0 + 8) * 132 + c0 + 1] = acc[i][j][3];
        }
    }
    __syncthreads();

    if (mode == 3) {
        #pragma unroll
        for (int it = 0; it < 16; it++) {
            int f = it * 256 + tid;
            int r = f >> 5, c4 = (f & 31) << 2;
            float4 v = *(float4*)&Osm[r * 132 + c4];
            *(float4*)&D[(size_t)(m0 + r) * HIDDEN + n0 + c4] = v;
        }
    } else {
        int h = (n0 >> 7) & 15;
        const float scale = (mode == 0) ? 0.08838834764831845f : 1.0f;
        bool rope = (mode <= 1);
        #pragma unroll
        for (int it = 0; it < 32; it++) {
            int f = it * 256 + tid;
            int r = f >> 6, i = f & 63;
            int m = m0 + r;
            int b = m >> 11, s = m & (SEQ - 1);
            float x1 = Osm[r * 132 + i], x2 = Osm[r * 132 + i + 64];
            float o1, o2;
            if (rope) {
                float c = g_cos[s * 64 + i], sn = g_sin[s * 64 + i];
                o1 = (x1 * c - x2 * sn) * scale;
                o2 = (x2 * c + x1 * sn) * scale;
            } else { o1 = x1; o2 = x2; }
            size_t o = ((size_t)(b * HEADS + h) * SEQ + s) * HD + i;
            D[o] = o1; D[o + 64] = o2;
        }
    }
}

// ---------------- Flash-style causal attention (f32x2 FFMA path) ------------
#define QPAD 132
#define SPAD 68
#define ATTN_SMEM_FLOATS (64*QPAD + 64*QPAD + 64*HD + 64*SPAD + 3*64)
#define ATTN_SMEM_BYTES  (ATTN_SMEM_FLOATS * 4)

__global__ __launch_bounds__(256)
void attn_kernel()
{
    extern __shared__ float sm[];
    float* Qs   = sm;                    // [64][132], q-scale fused in GEMM epilogue
    float* Ks   = Qs + 64 * QPAD;
    float* Vs   = Ks + 64 * QPAD;
    float* Ss   = Vs + 64 * HD;
    float* mrow = Ss + 64 * SPAD;
    float* lrow = mrow + 64;
    float* crow = lrow + 64;

    int tid = threadIdx.x;
    int tc = tid & 15, tr = tid >> 4;
    int qt = gridDim.x - 1 - blockIdx.x;
    int bh = blockIdx.y;
    long qbase = ((long)bh * SEQ + (long)qt * 64) * HD;

    #pragma unroll
    for (int it = 0; it < 8; it++) {
        int f = it * 256 + tid;
        int r = f >> 5, c4 = (f & 31) << 2;
        *(float4*)&Qs[r * QPAD + c4] = *(const float4*)&g_q[qbase + (long)r * HD + c4];
    }
    if (tid < 64) { mrow[tid] = -__int_as_float(0x7f800000); lrow[tid] = 0.f; }

    ull accO[4][8];
    #pragma unroll
    for (int i = 0; i < 4; i++)
        #pragma unroll
        for (int u = 0; u < 8; u++) accO[i][u] = 0ULL;

    __syncthreads();

    for (int kt = 0; kt <= qt; kt++) {
        long kvbase = ((long)bh * SEQ + (long)kt * 64) * HD;
        #pragma unroll
        for (int it = 0; it < 8; it++) {
            int f = it * 256 + tid;
            int r = f >> 5, c4 = (f & 31) << 2;
            *(float4*)&Ks[r * QPAD + c4] = *(const float4*)&g_k[kvbase + (long)r * HD + c4];
            *(float4*)&Vs[r * HD  + c4] = *(const float4*)&g_v[kvbase + (long)r * HD + c4];
        }
        __syncthreads();

        ull sacc[4][4];
        #pragma unroll
        for (int i = 0; i < 4; i++)
            #pragma unroll
            for (int j = 0; j < 4; j++) sacc[i][j] = 0ULL;

        #pragma unroll 8
        for (int k = 0; k < HD; k += 2) {
            ull q2[4], k2[4];
            #pragma unroll
            for (int i = 0; i < 4; i++)
                q2[i] = *(const ull*)&Qs[(tr * 4 + i) * QPAD + k];
            #pragma unroll
            for (int j = 0; j < 4; j++)
                k2[j] = *(const ull*)&Ks[(tc + 16 * j) * QPAD + k];
            #pragma unroll
            for (int i = 0; i < 4; i++)
                #pragma unroll
                for (int j = 0; j < 4; j++)
                    fma2(sacc[i][j], q2[i], k2[j]);
        }

        bool diag = (kt == qt);
        #pragma unroll
        for (int i = 0; i < 4; i++) {
            int r = tr * 4 + i;
            #pragma unroll
            for (int j = 0; j < 4; j++) {
                int c = tc + 16 * j;
                float lo, hi; unpack2(sacc[i][j], lo, hi);
                float v = lo + hi;
                if (diag && c > r) v = -__int_as_float(0x7f800000);
                Ss[r * SPAD + c] = v;
            }
        }
        __syncthreads();

        if (tid < 64) {
            int r = tid;
            float mo = mrow[r];
            float mx = mo;
            #pragma unroll 8
            for (int c = 0; c < 64; c++) mx = fmaxf(mx, Ss[r * SPAD + c]);
            float co = __expf(mo - mx);
            float sum = 0.f;
            #pragma unroll 8
            for (int c = 0; c < 64; c++) {
                float p = __expf(Ss[r * SPAD + c] - mx);
                Ss[r * SPAD + c] = p;
                sum += p;
            }
            crow[r] = co;
            lrow[r] = lrow[r] * co + sum;
            mrow[r] = mx;
        }
        __syncthreads();

        #pragma unroll
        for (int i = 0; i < 4; i++) {
            float cf = crow[tr * 4 + i];
            ull cf2 = pack2(cf, cf);
            #pragma unroll
            for (int u = 0; u < 8; u++) mul2(accO[i][u], accO[i][u], cf2);
        }
        #pragma unroll 4
        for (int kk = 0; kk < 64; kk += 2) {
            ull p2[4];
            #pragma unroll
            for (int i = 0; i < 4; i++)
                p2[i] = *(const ull*)&Ss[(tr * 4 + i) * SPAD + kk];
            #pragma unroll
            for (int u = 0; u < 8; u++) {
                int c = tc + 16 * u;
                ull v2 = pack2(Vs[kk * HD + c], Vs[(kk + 1) * HD + c]);
                #pragma unroll
                for (int i = 0; i < 4; i++)
                    fma2(accO[i][u], p2[i], v2);
            }
        }
        __syncthreads();
    }

    int bb = bh >> 4, h = bh & 15;
    #pragma unroll
    for (int i = 0; i < 4; i++) {
        int r = tr * 4 + i;
        float invl = 1.0f / lrow[r];
        long rowbase = ((long)(bb * SEQ + qt * 64 + r)) * HIDDEN + h * HD;
        #pragma unroll
        for (int u = 0; u < 8; u++) {
            float lo, hi; unpack2(accO[i][u], lo, hi);
            g_ctx[rowbase + tc + 16 * u] = (lo + hi) * invl;
        }
    }
}

// ---------------- launcher --------------------------------------------------
extern "C" void kernel_launch(void* const* d_in, const int* in_sizes, int n_in,
                              void* d_out, int out_size)
{
    (void)in_sizes; (void)n_in; (void)out_size;
    const float* X  = (const float*)d_in[0];
    const float* wq = (const float*)d_in[1];
    const float* wk = (const float*)d_in[2];
    const float* wv = (const float*)d_in[3];
    const float* wo = (const float*)d_in[4];
    float* out = (float*)d_out;

    __nv_bfloat16 *xp, *wp, *cp;
    float *qp, *kp, *vp, *ctxp;
    cudaGetSymbolAddress((void**)&xp, g_Xp);
    cudaGetSymbolAddress((void**)&wp, g_Wp);
    cudaGetSymbolAddress((void**)&cp, g_Cp);
    cudaGetSymbolAddress((void**)&qp, g_q);
    cudaGetSymbolAddress((void**)&kp, g_k);
    cudaGetSymbolAddress((void**)&vp, g_v);
    cudaGetSymbolAddress((void**)&ctxp, g_ctx);
    __nv_bfloat16* wps[4];
    for (int i = 0; i < 4; i++) wps[i] = wp + (size_t)i * HIDDEN * K3;

    cudaFuncSetAttribute(gemm_mma, cudaFuncAttributeMaxDynamicSharedMemorySize, G_SMEM_BYTES);
    cudaFuncSetAttribute(attn_kernel, cudaFuncAttributeMaxDynamicSharedMemorySize, ATTN_SMEM_BYTES);

    rope_table_kernel<<<(SEQ * 64 + 255) / 256, 256>>>();

    convert_split<<<(MTOT * HIDDEN + 255) / 256, 256>>>(X,  xp,     MTOT,   0);
    convert_split<<<(HIDDEN * HIDDEN + 255) / 256, 256>>>(wq, wps[0], HIDDEN, 1);
    convert_split<<<(HIDDEN * HIDDEN + 255) / 256, 256>>>(wk, wps[1], HIDDEN, 1);
    convert_split<<<(HIDDEN * HIDDEN + 255) / 256, 256>>>(wv, wps[2], HIDDEN, 1);
    convert_split<<<(HIDDEN * HIDDEN + 255) / 256, 256>>>(wo, wps[3], HIDDEN, 1);

    // fused QKV projections + RoPE/scale epilogue
    gemm_mma<<<dim3(48, 32), 256, G_SMEM_BYTES>>>(xp, wps[0], wps[1], wps[2],
                                                  qp, kp, vp, 1);

    attn_kernel<<<dim3(SEQ / 64, NB * HEADS), 256, ATTN_SMEM_BYTES>>>();

    convert_split<<<(MTOT * HIDDEN + 255) / 256, 256>>>(ctxp, cp, MTOT, 0);

    gemm_mma<<<dim3(16, 32), 256, G_SMEM_BYTES>>>(cp, wps[3], wps[3], wps[3],
                                                  out, out, out, 0);
}

// round 4
// speedup vs baseline: 1.7504x; 1.0978x over previous
#include <cuda_runtime.h>
#include <cuda_bf16.h>
#include <cstdint>

typedef unsigned long long ull;

#define HIDDEN 2048
#define K3     6144          // 3 * HIDDEN (bf16x3 split along K)
#define HEADS  16
#define HD     128
#define NB     2
#define SEQ    2048
#define MTOT   4096
#define BK     64
#define NSTAGE (K3/BK)       // 96

// ---------------- scratch ----------------------------------------------------
__device__ __align__(128) __nv_bfloat16 g_Xp[(size_t)MTOT*K3];
__device__ __align__(128) __nv_bfloat16 g_Wp[4][(size_t)HIDDEN*K3];
__device__ __align__(128) __nv_bfloat16 g_Cp[(size_t)MTOT*K3];   // attn out, split
__device__ float g_q[(size_t)NB*HEADS*SEQ*HD];     // [B,H,S,Hd] rope+scale applied
__device__ float g_k[(size_t)NB*HEADS*SEQ*HD];
__device__ float g_v[(size_t)NB*HEADS*SEQ*HD];
__device__ float g_cos[SEQ*64];
__device__ float g_sin[SEQ*64];

// ---------------- helpers ----------------------------------------------------
__device__ __forceinline__ ull pack2(float lo, float hi) {
    ull d;
    asm("mov.b64 %0, {%1, %2};" : "=l"(d)
        : "r"(__float_as_uint(lo)), "r"(__float_as_uint(hi)));
    return d;
}
__device__ __forceinline__ void unpack2(ull d, float& lo, float& hi) {
    unsigned a, b;
    asm("mov.b64 {%0, %1}, %2;" : "=r"(a), "=r"(b) : "l"(d));
    lo = __uint_as_float(a); hi = __uint_as_float(b);
}
__device__ __forceinline__ void fma2(ull& c, ull a, ull b) {
    asm("fma.rn.f32x2 %0, %1, %2, %3;" : "=l"(c) : "l"(a), "l"(b), "l"(c));
}
__device__ __forceinline__ void mul2(ull& c, ull a, ull b) {
    asm("mul.rn.f32x2 %0, %1, %2;" : "=l"(c) : "l"(a), "l"(b), "l"(c));
}
__device__ __forceinline__ void mma16816(float* c, const uint32_t* a, const uint32_t* b) {
    asm volatile(
        "mma.sync.aligned.m16n8k16.row.col.f32.bf16.bf16.f32 "
        "{%0,%1,%2,%3}, {%4,%5,%6,%7}, {%8,%9}, {%0,%1,%2,%3};"
        : "+f"(c[0]), "+f"(c[1]), "+f"(c[2]), "+f"(c[3])
        : "r"(a[0]), "r"(a[1]), "r"(a[2]), "r"(a[3]), "r"(b[0]), "r"(b[1]));
}
__device__ __forceinline__ void cp_async16(uint32_t saddr, const void* gaddr) {
    asm volatile("cp.async.ca.shared.global [%0], [%1], 16;"
                 :: "r"(saddr), "l"(gaddr));
}
#define CP_COMMIT() asm volatile("cp.async.commit_group;" ::: "memory")
#define CP_WAIT(n)  asm volatile("cp.async.wait_group %0;" :: "n"(n) : "memory")
#define LDMX4(d0,d1,d2,d3,addr) \
    asm volatile("ldmatrix.sync.aligned.m8n8.x4.shared.b16 {%0,%1,%2,%3}, [%4];" \
                 : "=r"(d0), "=r"(d1), "=r"(d2), "=r"(d3) : "r"(addr))
__device__ __forceinline__ uint32_t smem_u32(const void* p) {
    uint32_t a;
    asm("{ .reg .u64 t; cvta.to.shared.u64 t, %1; cvt.u32.u64 %0, t; }" : "=r"(a) : "l"(p));
    return a;
}

// ---------------- RoPE table -------------------------------------------------
__global__ void rope_table_kernel() {
    int idx = blockIdx.x * blockDim.x + threadIdx.x;
    if (idx >= SEQ * 64) return;
    int s = idx >> 6, i = idx & 63;
    double invf = pow(10000.0, -(double)i / 64.0);
    double ang = (double)s * invf;
    g_cos[idx] = (float)cos(ang);
    g_sin[idx] = (float)sin(ang);
}

// ---------------- bf16x3 split conversion (float4 vectorized) ----------------
// wmode=0 (A): [k]=hi, [2048+k]=hi, [4096+k]=lo
// wmode=1 (W): [k]=hi, [2048+k]=lo, [4096+k]=hi
__global__ void convert_split(const float* __restrict__ src,
                              __nv_bfloat16* __restrict__ dst,
                              int rows, int wmode) {
    long idx = (long)blockIdx.x * blockDim.x + threadIdx.x;   // one float4
    if (idx >= (long)rows * (HIDDEN / 4)) return;
    long r = idx >> 9;               // / 512
    int k = (int)(idx & 511) << 2;
    float4 x = ((const float4*)src)[idx];
    __nv_bfloat16 h0 = __float2bfloat16(x.x), h1 = __float2bfloat16(x.y);
    __nv_bfloat16 h2 = __float2bfloat16(x.z), h3 = __float2bfloat16(x.w);
    __nv_bfloat16 l0 = __float2bfloat16(x.x - __bfloat162float(h0));
    __nv_bfloat16 l1 = __float2bfloat16(x.y - __bfloat162float(h1));
    __nv_bfloat16 l2 = __float2bfloat16(x.z - __bfloat162float(h2));
    __nv_bfloat16 l3 = __float2bfloat16(x.w - __bfloat162float(h3));
    __nv_bfloat16 hv[4] = {h0, h1, h2, h3};
    __nv_bfloat16 lv[4] = {l0, l1, l2, l3};
    __nv_bfloat16* d = dst + r * K3;
    uint2 hp = *(uint2*)hv, lp = *(uint2*)lv;
    *(uint2*)&d[k] = hp;
    *(uint2*)&d[HIDDEN + k]     = wmode ? lp : hp;
    *(uint2*)&d[2 * HIDDEN + k] = wmode ? hp : lp;
}

// ---------------- mma.sync GEMM: D[M,N] = A'[M,K3] * W'[N,K3]^T ---------------
// 128x128 tile, 256 threads (2x4 warps), BK=64, cp.async double buffer, ldmatrix.
#define TILE_STRIDE 144                   // 128B data + 16B pad per 64-bf16 row
#define ST          (128*TILE_STRIDE)     // 18432 per tile buffer
#define G_SMEM_BYTES (4*ST)               // 73728; epilogue Osm (67584) aliases

__global__ __launch_bounds__(256, 2)
void gemm_mma(const __nv_bfloat16* __restrict__ A,
              const __nv_bfloat16* __restrict__ Wq,
              const __nv_bfloat16* __restrict__ Wk,
              const __nv_bfloat16* __restrict__ Wv,
              float* __restrict__ Dq, float* __restrict__ Dk, float* __restrict__ Dv,
              int fused)
{
    extern __shared__ char smem[];
    uint32_t sb = smem_u32(smem);
    int tid = threadIdx.x;
    int wid = tid >> 5, lane = tid & 31;
    int warpm = wid >> 2, warpn = wid & 3;
    int lrw = lane >> 2, lk = lane & 3;     // c-fragment coords

    const __nv_bfloat16* W; float* D; int n0, mode;
    if (fused) {
        int which = blockIdx.x >> 4;
        n0 = (blockIdx.x & 15) * 128;
        W = (which == 0) ? Wq : (which == 1) ? Wk : Wv;
        D = (which == 0) ? Dq : (which == 1) ? Dk : Dv;
        mode = which;
    } else {
        n0 = blockIdx.x * 128; W = Wq; D = Dq; mode = 3;
    }
    int m0 = blockIdx.y * 128;

    const char* Ab = (const char*)(A + (size_t)m0 * K3);
    const char* Bb = (const char*)(W + (size_t)n0 * K3);

    float acc[4][4][4];
    #pragma unroll
    for (int i = 0; i < 4; i++)
        #pragma unroll
        for (int j = 0; j < 4; j++)
            #pragma unroll
            for (int r = 0; r < 4; r++) acc[i][j][r] = 0.f;

    int ld_r = tid >> 1, ld_c = (tid & 1) * 64;
    auto issue_stage = [&](int kelem, int buf) {
        uint32_t sA = sb + buf * ST + ld_r * TILE_STRIDE + ld_c;
        uint32_t sB = sA + 2 * ST;
        const char* gA = Ab + (size_t)kelem * 2 + (size_t)ld_r * (K3 * 2) + ld_c;
        const char* gB = Bb + (size_t)kelem * 2 + (size_t)ld_r * (K3 * 2) + ld_c;
        #pragma unroll
        for (int j = 0; j < 4; j++) {
            cp_async16(sA + j * 16, gA + j * 16);
            cp_async16(sB + j * 16, gB + j * 16);
        }
        CP_COMMIT();
    };

    // ldmatrix lane address offsets
    uint32_t aOff = (uint32_t)((warpm * 64 + (lane & 15)) * TILE_STRIDE + ((lane >> 4) << 4));
    uint32_t bOff = (uint32_t)((warpn * 32 + (lane & 7) + ((lane >> 4) << 3)) * TILE_STRIDE
                               + (((lane >> 3) & 1) << 4));

    issue_stage(0, 0);

    for (int st = 0; st < NSTAGE; st++) {
        if (st + 1 < NSTAGE) { issue_stage((st + 1) * BK, (st + 1) & 1); CP_WAIT(1); }
        else                 { CP_WAIT(0); }
        __syncthreads();

        uint32_t aB = sb + (st & 1) * ST + aOff;
        uint32_t bB = sb + 2 * ST + (st & 1) * ST + bOff;

        #pragma unroll
        for (int s = 0; s < 4; s++) {               // four k16 steps per BK=64
            uint32_t af[4][4], bf[4][2];
            #pragma unroll
            for (int i = 0; i < 4; i++)
                LDMX4(af[i][0], af[i][1], af[i][2], af[i][3],
                      aB + i * 16 * TILE_STRIDE + s * 32);
            #pragma unroll
            for (int p = 0; p < 2; p++) {
                uint32_t r0, r1, r2, r3;
                LDMX4(r0, r1, r2, r3, bB + p * 16 * TILE_STRIDE + s * 32);
                bf[2 * p][0] = r0; bf[2 * p][1] = r1;
                bf[2 * p + 1][0] = r2; bf[2 * p + 1][1] = r3;
            }
            #pragma unroll
            for (int i = 0; i < 4; i++)
                #pragma unroll
                for (int j = 0; j < 4; j++)
                    mma16816(acc[i][j], af[i], bf[j]);
        }
        __syncthreads();
    }

    // ---- epilogue: regs -> Osm, then fused RoPE/scale writes ----
    float* Osm = (float*)smem;
    #pragma unroll
    for (int i = 0; i < 4; i++) {
        int r0 = warpm * 64 + i * 16 + lrw;
        #pragma unroll
        for (int j = 0; j < 4; j++) {
            int c0 = warpn * 32 + j * 8 + lk * 2;
            Osm[r0 * 132 + c0]           = acc[i][j][0];
            Osm[r0 * 132 + c0 + 1]       = acc[i][j][1];
            Osm[(r0 + 8) * 132 + c0]     = acc[i][j][2];
            Osm[(r0 + 8) * 132 + c0 + 1] = acc[i][j][3];
        }
    }
    __syncthreads();

    if (mode == 3) {
        #pragma unroll
        for (int it = 0; it < 16; it++) {
            int f = it * 256 + tid;
            int r = f >> 5, c4 = (f & 31) << 2;
            float4 v = *(float4*)&Osm[r * 132 + c4];
            *(float4*)&D[(size_t)(m0 + r) * HIDDEN + n0 + c4] = v;
        }
    } else {
        int h = (n0 >> 7) & 15;
        const float scale = (mode == 0) ? 0.08838834764831845f : 1.0f;
        bool rope = (mode <= 1);
        #pragma unroll
        for (int it = 0; it < 32; it++) {
            int f = it * 256 + tid;
            int r = f >> 6, i = f & 63;
            int m = m0 + r;
            int b = m >> 11, s = m & (SEQ - 1);
            float x1 = Osm[r * 132 + i], x2 = Osm[r * 132 + i + 64];
            float o1, o2;
            if (rope) {
                float c = g_cos[s * 64 + i], sn = g_sin[s * 64 + i];
                o1 = (x1 * c - x2 * sn) * scale;
                o2 = (x2 * c + x1 * sn) * scale;
            } else { o1 = x1; o2 = x2; }
            size_t o = ((size_t)(b * HEADS + h) * SEQ + s) * HD + i;
            D[o] = o1; D[o + 64] = o2;
        }
    }
}

// ---------------- Flash-style causal attention -------------------------------
// f32x2 FFMA math; cp.async double-buffered KV; warp-local shfl softmax.
#define QPAD 132
#define SPAD 68
#define QS_F   (64*QPAD)            // 8448
#define KS_F   (64*QPAD)            // 8448 per buffer
#define VS_F   (64*HD)              // 8192 per buffer
#define OFF_K  QS_F
#define OFF_V  (QS_F + 2*KS_F)
#define OFF_S  (OFF_V + 2*VS_F)
#define OFF_M  (OFF_S + 64*SPAD)
#define OFF_L  (OFF_M + 64)
#define ATTN_SMEM_FLOATS (OFF_L + 64)
#define ATTN_SMEM_BYTES  (ATTN_SMEM_FLOATS * 4)
#define NEGINF __int_as_float(0xff800000)

__global__ __launch_bounds__(256)
void attn_kernel()
{
    extern __shared__ float sm[];
    float* Qs   = sm;
    float* mrow = sm + OFF_M;
    float* lrow = sm + OFF_L;
    float* Ss   = sm + OFF_S;
    uint32_t sb = smem_u32(sm);

    int tid = threadIdx.x;
    int tc = tid & 15, tr = tid >> 4;
    int qt = gridDim.x - 1 - blockIdx.x;
    int bh = blockIdx.y;
    long qbase = ((long)bh * SEQ + (long)qt * 64) * HD;

    // load Q tile (scale already fused in GEMM epilogue)
    #pragma unroll
    for (int it = 0; it < 8; it++) {
        int f = it * 256 + tid;
        int r = f >> 5, c4 = (f & 31) << 2;
        *(float4*)&Qs[r * QPAD + c4] = *(const float4*)&g_q[qbase + (long)r * HD + c4];
    }
    if (tid < 64) { mrow[tid] = NEGINF; lrow[tid] = 0.f; }

    // cp.async KV stage loader: 4 threads/row, 8 16B chunks each
    int kv_r = tid >> 2;
    int kv_c = (tid & 3) * 16;          // byte offset of first chunk (x4 stride 64B)
    auto issue_kv = [&](int kt, int buf) {
        long kvbase = ((long)bh * SEQ + (long)kt * 64) * HD;
        const char* gK = (const char*)(g_k + kvbase + kv_r * HD) + kv_c;
        const char* gV = (const char*)(g_v + kvbase + kv_r * HD) + kv_c;
        uint32_t sK = sb + (OFF_K + buf * KS_F) * 4 + kv_r * (QPAD * 4) + kv_c;
        uint32_t sV = sb + (OFF_V + buf * VS_F) * 4 + kv_r * (HD * 4) + kv_c;
        #pragma unroll
        for (int j = 0; j < 8; j++) {
            cp_async16(sK + j * 64, gK + j * 64);
            cp_async16(sV + j * 64, gV + j * 64);
        }
        CP_COMMIT();
    };

    ull accO[4][8];
    #pragma unroll
    for (int i = 0; i < 4; i++)
        #pragma unroll
        for (int u = 0; u < 8; u++) accO[i][u] = 0ULL;

    issue_kv(0, 0);

    for (int kt = 0; kt <= qt; kt++) {
        if (kt + 1 <= qt) { issue_kv(kt + 1, (kt + 1) & 1); CP_WAIT(1); }
        else              { CP_WAIT(0); }
        __syncthreads();

        const float* KsB = sm + OFF_K + (kt & 1) * KS_F;
        const float* VsB = sm + OFF_V + (kt & 1) * VS_F;

        // ---- scores ----
        ull sacc[4][4];
        #pragma unroll
        for (int i = 0; i < 4; i++)
            #pragma unroll
            for (int j = 0; j < 4; j++) sacc[i][j] = 0ULL;

        #pragma unroll 8
        for (int k = 0; k < HD; k += 2) {
            ull q2[4], k2[4];
            #pragma unroll
            for (int i = 0; i < 4; i++)
                q2[i] = *(const ull*)&Qs[(tr * 4 + i) * QPAD + k];
            #pragma unroll
            for (int j = 0; j < 4; j++)
                k2[j] = *(const ull*)&KsB[(tc + 16 * j) * QPAD + k];
            #pragma unroll
            for (int i = 0; i < 4; i++)
                #pragma unroll
                for (int j = 0; j < 4; j++)
                    fma2(sacc[i][j], q2[i], k2[j]);
        }

        // ---- warp-local online softmax (row group = 16 lanes, same tr) ----
        bool diag = (kt == qt);
        float co[4];
        #pragma unroll
        for (int i = 0; i < 4; i++) {
            int r = tr * 4 + i;
            float pv[4], m = NEGINF;
            #pragma unroll
            for (int j = 0; j < 4; j++) {
                int c = tc + 16 * j;
                float lo, hi; unpack2(sacc[i][j], lo, hi);
                float v = lo + hi;
                if (diag && c > r) v = NEGINF;
                pv[j] = v;
                m = fmaxf(m, v);
            }
            #pragma unroll
            for (int o = 8; o; o >>= 1) m = fmaxf(m, __shfl_xor_sync(0xffffffffu, m, o));
            float mo = mrow[r];
            float mx = fmaxf(m, mo);
            co[i] = __expf(mo - mx);
            float sum = 0.f;
            #pragma unroll
            for (int j = 0; j < 4; j++) {
                float p = __expf(pv[j] - mx);
                Ss[r * SPAD + tc + 16 * j] = p;
                sum += p;
            }
            #pragma unroll
            for (int o = 8; o; o >>= 1) sum += __shfl_xor_sync(0xffffffffu, sum, o);
            if (tc == 0) { mrow[r] = mx; lrow[r] = lrow[r] * co[i] + sum; }
        }
        __syncwarp();

        // ---- rescale + P@V ----
        #pragma unroll
        for (int i = 0; i < 4; i++) {
            ull c2 = pack2(co[i], co[i]);
            #pragma unroll
            for (int u = 0; u < 8; u++) mul2(accO[i][u], accO[i][u], c2);
        }
        #pragma unroll 4
        for (int kk = 0; kk < 64; kk += 2) {
            ull p2[4];
            #pragma unroll
            for (int i = 0; i < 4; i++)
                p2[i] = *(const ull*)&Ss[(tr * 4 + i) * SPAD + kk];
            #pragma unroll
            for (int u = 0; u < 8; u++) {
                int c = tc + 16 * u;
                ull v2 = pack2(VsB[kk * HD + c], VsB[(kk + 1) * HD + c]);
                #pragma unroll
                for (int i = 0; i < 4; i++)
                    fma2(accO[i][u], p2[i], v2);
            }
        }
        __syncthreads();
    }

    // ---- epilogue: normalize + fused bf16x3 split write into g_Cp ----
    __syncwarp();
    int bb = bh >> 4, h = bh & 15;
    #pragma unroll
    for (int i = 0; i < 4; i++) {
        int r = tr * 4 + i;
        float invl = 1.0f / lrow[r];
        size_t row = (size_t)bb * SEQ + (size_t)qt * 64 + r;
        __nv_bfloat16* d = g_Cp + row * K3;
        #pragma unroll
        for (int u = 0; u < 8; u++) {
            float lo, hi; unpack2(accO[i][u], lo, hi);
            float val = (lo + hi) * invl;
            int k = h * HD + tc + 16 * u;
            __nv_bfloat16 hb = __float2bfloat16(val);
            __nv_bfloat16 lb = __float2bfloat16(val - __bfloat162float(hb));
            d[k] = hb;                 // A-operand layout: [hi|hi|lo]
            d[HIDDEN + k] = hb;
            d[2 * HIDDEN + k] = lb;
        }
    }
}

// ---------------- launcher ----------------------------------------------------
extern "C" void kernel_launch(void* const* d_in, const int* in_sizes, int n_in,
                              void* d_out, int out_size)
{
    (void)in_sizes; (void)n_in; (void)out_size;
    const float* X  = (const float*)d_in[0];
    const float* wq = (const float*)d_in[1];
    const float* wk = (const float*)d_in[2];
    const float* wv = (const float*)d_in[3];
    const float* wo = (const float*)d_in[4];
    float* out = (float*)d_out;

    __nv_bfloat16 *xp, *wp, *cp;
    float *qp, *kp, *vp;
    cudaGetSymbolAddress((void**)&xp, g_Xp);
    cudaGetSymbolAddress((void**)&wp, g_Wp);
    cudaGetSymbolAddress((void**)&cp, g_Cp);
    cudaGetSymbolAddress((void**)&qp, g_q);
    cudaGetSymbolAddress((void**)&kp, g_k);
    cudaGetSymbolAddress((void**)&vp, g_v);
    __nv_bfloat16* wps[4];
    for (int i = 0; i < 4; i++) wps[i] = wp + (size_t)i * HIDDEN * K3;

    cudaFuncSetAttribute(gemm_mma, cudaFuncAttributeMaxDynamicSharedMemorySize, G_SMEM_BYTES);
    cudaFuncSetAttribute(attn_kernel, cudaFuncAttributeMaxDynamicSharedMemorySize, ATTN_SMEM_BYTES);

    rope_table_kernel<<<(SEQ * 64 + 255) / 256, 256>>>();

    convert_split<<<(MTOT * HIDDEN / 4 + 255) / 256, 256>>>(X,  xp,     MTOT,   0);
    convert_split<<<(HIDDEN * HIDDEN / 4 + 255) / 256, 256>>>(wq, wps[0], HIDDEN, 1);
    convert_split<<<(HIDDEN * HIDDEN / 4 + 255) / 256, 256>>>(wk, wps[1], HIDDEN, 1);
    convert_split<<<(HIDDEN * HIDDEN / 4 + 255) / 256, 256>>>(wv, wps[2], HIDDEN, 1);
    convert_split<<<(HIDDEN * HIDDEN / 4 + 255) / 256, 256>>>(wo, wps[3], HIDDEN, 1);

    // fused QKV projections + RoPE/scale epilogue
    gemm_mma<<<dim3(48, 32), 256, G_SMEM_BYTES>>>(xp, wps[0], wps[1], wps[2],
                                                  qp, kp, vp, 1);

    // attention (writes bf16x3-split ctx directly)
    attn_kernel<<<dim3(SEQ / 64, NB * HEADS), 256, ATTN_SMEM_BYTES>>>();

    // output projection -> d_out
    gemm_mma<<<dim3(16, 32), 256, G_SMEM_BYTES>>>(cp, wps[3], wps[3], wps[3],
                                                  out, out, out, 0);
}